// round 1
// baseline (speedup 1.0000x reference)
#include <cuda_runtime.h>

// FP8 E4M3 multiplier over "bit-vector" encoded tensors.
// Each fp8 value is 8 float32 bits [s, e3, e2, e1, e0, m2, m1, m0].
// n = 1024*4096 elements; pure streaming: 32B+32B in, 32B out per element.

__device__ __forceinline__ int fbit(float f) { return f != 0.0f ? 1 : 0; }

// round-to-nearest-even right shift of non-negative M by sh (sh >= 1)
__device__ __forceinline__ int rne_rshift(int M, int sh) {
    int q = M >> sh;
    int rem = M - (q << sh);
    int half = 1 << (sh - 1);
    int up = (rem > half) | ((rem == half) & (q & 1));
    return q + up;
}

__global__ void __launch_bounds__(256) fp8mul_kernel(
    const float4* __restrict__ a4,
    const float4* __restrict__ b4,
    float4* __restrict__ o4,
    int n)
{
    int i = blockIdx.x * blockDim.x + threadIdx.x;
    if (i >= n) return;

    float4 alo = a4[2 * i], ahi = a4[2 * i + 1];
    float4 blo = b4[2 * i], bhi = b4[2 * i + 1];

    // decode a
    int sa = fbit(alo.x);
    int ea = (fbit(alo.y) << 3) | (fbit(alo.z) << 2) | (fbit(alo.w) << 1) | fbit(ahi.x);
    int ma = (fbit(ahi.y) << 2) | (fbit(ahi.z) << 1) | fbit(ahi.w);
    // decode b
    int sb = fbit(blo.x);
    int eb = (fbit(blo.y) << 3) | (fbit(blo.z) << 2) | (fbit(blo.w) << 1) | fbit(bhi.x);
    int mb = (fbit(bhi.y) << 2) | (fbit(bhi.z) << 1) | fbit(bhi.w);

    int sig_a = (ea == 0) ? ma : (ma + 8);
    int sig_b = (eb == 0) ? mb : (mb + 8);
    int exa = ((ea == 0) ? 1 : ea) - 7;
    int exb = ((eb == 0) ? 1 : eb) - 7;

    int M = sig_a * sig_b;          // exact product, <= 225
    int E = exa + exb - 6;          // value = M * 2^E

    // MSB position p of M (0 for M in {0,1})
    int p = (M > 0) ? (31 - __clz(M)) : 0;
    int eb_out = E + p + 7;

    // ---- normal path: RNE round to 3 mantissa bits ----
    int sh = p - 3;
    int mant4;
    if (sh > 0)      mant4 = rne_rshift(M, sh);
    else             mant4 = M << (-sh);
    int carry = mant4 >> 4;                 // rounding overflow
    if (mant4 == 16) mant4 = 8;
    int e_n = eb_out + carry;
    int m_n = mant4 - 8;
    if (e_n >= 16) { e_n = 15; m_n = 7; }   // overflow -> NaN pattern

    // ---- subnormal path (eb_out <= 0): mant = RNE(M * 2^(E+9)) ----
    int t = E + 9;
    int mant_s;
    if (t >= 0) {
        mant_s = M << t;                    // in sub path always < 8, no overflow
    } else {
        int shs = (-t < 30) ? -t : 30;
        mant_s = rne_rshift(M, shs);
    }
    int e_s = (mant_s >= 8) ? 1 : 0;
    int m_s = (mant_s >= 8) ? 0 : mant_s;

    // ---- select ----
    bool is_sub = (eb_out <= 0);
    int e_o = is_sub ? e_s : e_n;
    int m_o = is_sub ? m_s : m_n;
    if (M == 0) { e_o = 0; m_o = 0; }
    int s_o = sa ^ sb;

    float4 olo, ohi;
    olo.x = (float)s_o;
    olo.y = (float)((e_o >> 3) & 1);
    olo.z = (float)((e_o >> 2) & 1);
    olo.w = (float)((e_o >> 1) & 1);
    ohi.x = (float)(e_o & 1);
    ohi.y = (float)((m_o >> 2) & 1);
    ohi.z = (float)((m_o >> 1) & 1);
    ohi.w = (float)(m_o & 1);

    o4[2 * i]     = olo;
    o4[2 * i + 1] = ohi;
}

extern "C" void kernel_launch(void* const* d_in, const int* in_sizes, int n_in,
                              void* d_out, int out_size)
{
    const float4* a = (const float4*)d_in[0];
    const float4* b = (const float4*)d_in[1];
    float4* o = (float4*)d_out;
    int n = in_sizes[0] / 8;                 // fp8 element count
    int threads = 256;
    int blocks = (n + threads - 1) / threads;
    fp8mul_kernel<<<blocks, threads>>>(a, b, o, n);
}